// round 13
// baseline (speedup 1.0000x reference)
#include <cuda_runtime.h>
#include <cuda_fp16.h>
#include <math.h>
#include <cstdint>

#define SEQ   4096
#define DM    768
#define NH    12
#define DH    64
#define QKVC  2304          // 3 * DM
#define QS    0.18033688011112042f   // (1/sqrt(64)) * log2(e): exp2-domain scores
#define NEG   -1.0e30f

// ------------------------- scratch (__device__ globals) --------------------
__device__ __half g_x16[SEQ * DM];          // x in fp16
__device__ __half g_win16[QKVC * DM];       // W_in fp16
__device__ __half g_wout16[DM * DM];        // W_out fp16
__device__ __half g_q16[NH * SEQ * DH];     // [h][s][d], pre-scaled by QS
__device__ __half g_k16[NH * SEQ * DH];
__device__ __half g_v16[NH * SEQ * DH];
__device__ __half g_attn16[SEQ * DM];       // attention out fp16

// ---------------------------- PTX helpers ----------------------------------
__device__ __forceinline__ uint32_t smem_u32(const void* p) {
    uint32_t a;
    asm("{ .reg .u64 t; cvta.to.shared.u64 t, %1; cvt.u32.u64 %0, t; }" : "=r"(a) : "l"(p));
    return a;
}
__device__ __forceinline__ void ldmx4(uint32_t* r, uint32_t addr) {
    asm volatile("ldmatrix.sync.aligned.m8n8.x4.shared.b16 {%0,%1,%2,%3}, [%4];"
        : "=r"(r[0]), "=r"(r[1]), "=r"(r[2]), "=r"(r[3]) : "r"(addr));
}
__device__ __forceinline__ void ldmx4t(uint32_t* r, uint32_t addr) {
    asm volatile("ldmatrix.sync.aligned.m8n8.x4.trans.shared.b16 {%0,%1,%2,%3}, [%4];"
        : "=r"(r[0]), "=r"(r[1]), "=r"(r[2]), "=r"(r[3]) : "r"(addr));
}
__device__ __forceinline__ void mma16816(float* d, const uint32_t* a,
                                         const uint32_t* b, const float* c) {
    asm volatile(
        "mma.sync.aligned.m16n8k16.row.col.f32.f16.f16.f32 "
        "{%0,%1,%2,%3}, {%4,%5,%6,%7}, {%8,%9}, {%10,%11,%12,%13};"
        : "=f"(d[0]), "=f"(d[1]), "=f"(d[2]), "=f"(d[3])
        : "r"(a[0]), "r"(a[1]), "r"(a[2]), "r"(a[3]),
          "r"(b[0]), "r"(b[1]),
          "f"(c[0]), "f"(c[1]), "f"(c[2]), "f"(c[3]));
}
__device__ __forceinline__ uint32_t packh2(float x, float y) {
    __half2 h = __floats2half2_rn(x, y);
    return *(uint32_t*)&h;
}
__device__ __forceinline__ float ex2(float x) {           // raw MUFU.EX2
    float y;
    asm("ex2.approx.f32 %0, %1;" : "=f"(y) : "f"(x));
    return y;
}
__device__ __forceinline__ uint32_t ex2h2(uint32_t x) {   // MUFU.EX2 on half2
    uint32_t y;
    asm("ex2.approx.f16x2 %0, %1;" : "=r"(y) : "r"(x));
    return y;
}
__device__ __forceinline__ __half2 u2h2(uint32_t x) { return *(__half2*)&x; }

#define GSTR 72   // smem row stride in halves (conflict-free ldmatrix + STS phases)

// ---------------------------------------------------------------------------
// fp32 -> fp16 convert, all three tensors in one launch (8 elems/thread)
// ---------------------------------------------------------------------------
#define CVT_S0 (SEQ * DM)
#define CVT_S1 (QKVC * DM)
#define CVT_S2 (DM * DM)

__device__ __forceinline__ void cvt8(const float* s, __half* d) {
    float4 a = *(const float4*)s;
    float4 b = *(const float4*)(s + 4);
    uint4 u;
    u.x = packh2(a.x, a.y); u.y = packh2(a.z, a.w);
    u.z = packh2(b.x, b.y); u.w = packh2(b.z, b.w);
    *(uint4*)d = u;
}

__global__ __launch_bounds__(256) void cvt_all(const float* __restrict__ x,
                                               const float* __restrict__ wi,
                                               const float* __restrict__ wo)
{
    int i = (blockIdx.x * 256 + threadIdx.x) * 8;
    if (i < CVT_S0) {
        cvt8(x + i, g_x16 + i);
    } else if (i < CVT_S0 + CVT_S1) {
        int j = i - CVT_S0;
        cvt8(wi + j, g_win16 + j);
    } else if (i < CVT_S0 + CVT_S1 + CVT_S2) {
        int j = i - CVT_S0 - CVT_S1;
        cvt8(wo + j, g_wout16 + j);
    }
}

// ---------------------------------------------------------------------------
// QKV GEMM (unchanged R11 winner): 128x128 CTA, 256 thr, warp 64x32, K-tile 64.
// ---------------------------------------------------------------------------
__global__ __launch_bounds__(256, 2) void gemm_qkv(
    const __half* __restrict__ A, const __half* __restrict__ B,
    const float* __restrict__ bias)
{
    __shared__ __half smA[128 * GSTR];
    __shared__ __half smB[128 * GSTR];

    const int tid  = threadIdx.x;
    const int lane = tid & 31;
    const int wid  = tid >> 5;
    const int m0   = blockIdx.y * 128;
    const int n0   = blockIdx.x * 128;
    const int wm   = (wid >> 2) * 64;
    const int wn   = (wid & 3) * 32;
    const int K    = DM;

    const uint32_t smAb = smem_u32(smA);
    const uint32_t smBb = smem_u32(smB);

    float Cf[4][4][4];
#pragma unroll
    for (int mt = 0; mt < 4; mt++)
#pragma unroll
        for (int nb = 0; nb < 4; nb++)
#pragma unroll
            for (int j = 0; j < 4; j++) Cf[mt][nb][j] = 0.f;

    for (int kt = 0; kt < K; kt += 64) {
#pragma unroll
        for (int i = 0; i < 4; i++) {
            int idx = i * 256 + tid;
            int row = idx >> 3;
            int g   = idx & 7;
            *(uint4*)(smA + row * GSTR + g * 8) =
                *(const uint4*)(A + (size_t)(m0 + row) * K + kt + g * 8);
            *(uint4*)(smB + row * GSTR + g * 8) =
                *(const uint4*)(B + (size_t)(n0 + row) * K + kt + g * 8);
        }
        __syncthreads();

        uint32_t bf[4][8];
#pragma unroll
        for (int nb = 0; nb < 4; nb++) {
            uint32_t rowa = wn + nb * 8 + (lane & 7);
            uint32_t cola = (lane >> 3) * 8;
            ldmx4(bf[nb],     smBb + (rowa * GSTR + cola) * 2);
            ldmx4(bf[nb] + 4, smBb + (rowa * GSTR + 32 + cola) * 2);
        }
#pragma unroll
        for (int mt = 0; mt < 4; mt++) {
            uint32_t af[4][4];
            uint32_t rowa = wm + mt * 16 + (lane & 15);
            uint32_t cola = (lane >> 4) * 8;
#pragma unroll
            for (int kb = 0; kb < 4; kb++)
                ldmx4(af[kb], smAb + (rowa * GSTR + kb * 16 + cola) * 2);
#pragma unroll
            for (int nb = 0; nb < 4; nb++)
#pragma unroll
                for (int kb = 0; kb < 4; kb++)
                    mma16816(Cf[mt][nb], af[kb], &bf[nb][2 * kb], Cf[mt][nb]);
        }
        __syncthreads();
    }

#pragma unroll
    for (int mt = 0; mt < 4; mt++) {
#pragma unroll
        for (int nb = 0; nb < 4; nb++) {
            int r0  = m0 + wm + mt * 16 + (lane >> 2);
            int col = n0 + wn + nb * 8 + (lane & 3) * 2;
            float b0v = bias[col], b1v = bias[col + 1];
            int seg  = col / DM;               // 0=Q 1=K 2=V
            int cm   = col - seg * DM;
            int head = cm >> 6, dim = cm & 63;
            __half* dst = (seg == 0) ? g_q16 : (seg == 1) ? g_k16 : g_v16;
            float sc = (seg == 0) ? QS : 1.f;
            __half2 w0 = __floats2half2_rn((Cf[mt][nb][0] + b0v) * sc,
                                           (Cf[mt][nb][1] + b1v) * sc);
            __half2 w1 = __floats2half2_rn((Cf[mt][nb][2] + b0v) * sc,
                                           (Cf[mt][nb][3] + b1v) * sc);
            *(__half2*)(dst + ((size_t)head * SEQ + r0) * DH + dim)     = w0;
            *(__half2*)(dst + ((size_t)head * SEQ + r0 + 8) * DH + dim) = w1;
        }
    }
}

// ---------------------------------------------------------------------------
// Out-proj GEMM (R12 winner): 128x64 CTA tile, 128 threads, 4 warps of 64x32.
// ---------------------------------------------------------------------------
__global__ __launch_bounds__(128, 4) void gemm_out(
    const __half* __restrict__ A, const __half* __restrict__ B,
    const float* __restrict__ bias, float* __restrict__ Cout)
{
    __shared__ __half smA[128 * GSTR];
    __shared__ __half smB[64 * GSTR];

    const int tid  = threadIdx.x;
    const int lane = tid & 31;
    const int wid  = tid >> 5;           // 0..3
    const int m0   = blockIdx.y * 128;
    const int n0   = blockIdx.x * 64;
    const int wm   = (wid >> 1) * 64;
    const int wn   = (wid & 1) * 32;
    const int K    = DM;
    const int N    = DM;

    const uint32_t smAb = smem_u32(smA);
    const uint32_t smBb = smem_u32(smB);

    float Cf[4][4][4];
#pragma unroll
    for (int mt = 0; mt < 4; mt++)
#pragma unroll
        for (int nb = 0; nb < 4; nb++)
#pragma unroll
            for (int j = 0; j < 4; j++) Cf[mt][nb][j] = 0.f;

    for (int kt = 0; kt < K; kt += 64) {
#pragma unroll
        for (int i = 0; i < 8; i++) {
            int idx = i * 128 + tid;
            int row = idx >> 3;
            int g   = idx & 7;
            *(uint4*)(smA + row * GSTR + g * 8) =
                *(const uint4*)(A + (size_t)(m0 + row) * K + kt + g * 8);
        }
#pragma unroll
        for (int i = 0; i < 4; i++) {
            int idx = i * 128 + tid;
            int row = idx >> 3;
            int g   = idx & 7;
            *(uint4*)(smB + row * GSTR + g * 8) =
                *(const uint4*)(B + (size_t)(n0 + row) * K + kt + g * 8);
        }
        __syncthreads();

        uint32_t bf[4][8];
#pragma unroll
        for (int nb = 0; nb < 4; nb++) {
            uint32_t rowa = wn + nb * 8 + (lane & 7);
            uint32_t cola = (lane >> 3) * 8;
            ldmx4(bf[nb],     smBb + (rowa * GSTR + cola) * 2);
            ldmx4(bf[nb] + 4, smBb + (rowa * GSTR + 32 + cola) * 2);
        }
#pragma unroll
        for (int mt = 0; mt < 4; mt++) {
            uint32_t af[4][4];
            uint32_t rowa = wm + mt * 16 + (lane & 15);
            uint32_t cola = (lane >> 4) * 8;
#pragma unroll
            for (int kb = 0; kb < 4; kb++)
                ldmx4(af[kb], smAb + (rowa * GSTR + kb * 16 + cola) * 2);
#pragma unroll
            for (int nb = 0; nb < 4; nb++)
#pragma unroll
                for (int kb = 0; kb < 4; kb++)
                    mma16816(Cf[mt][nb], af[kb], &bf[nb][2 * kb], Cf[mt][nb]);
        }
        __syncthreads();
    }

#pragma unroll
    for (int mt = 0; mt < 4; mt++) {
#pragma unroll
        for (int nb = 0; nb < 4; nb++) {
            int r0  = m0 + wm + mt * 16 + (lane >> 2);
            int col = n0 + wn + nb * 8 + (lane & 3) * 2;
            float b0v = bias[col], b1v = bias[col + 1];
            float2 w0 = make_float2(Cf[mt][nb][0] + b0v, Cf[mt][nb][1] + b1v);
            float2 w1 = make_float2(Cf[mt][nb][2] + b0v, Cf[mt][nb][3] + b1v);
            *(float2*)(Cout + (size_t)r0 * N + col)       = w0;
            *(float2*)(Cout + (size_t)(r0 + 8) * N + col) = w1;
        }
    }
}

// ---------------------------------------------------------------------------
// HMMA flash attention: 128 threads (4 warps), 64 q-rows/CTA, 4 CTAs/SM,
// 128-key staging, two 64-key sub-blocks per barrier pair.
// R13: fp16x2 softmax (ex2.f16x2 halves MUFU; results ARE the P A-frags;
// HADD2-tree row sums) + restored per-warp masked-tile skip guard.
// ---------------------------------------------------------------------------
#define KSTR 72
#define KVT128 (128 * KSTR)   // halves per 128-row K (or V) tile

__global__ __launch_bounds__(128, 4) void attn_mma_kernel()
{
    __shared__ __half sm[2 * KVT128];    // K[128] | V[128]  (36,864 B)

    const int tid  = threadIdx.x;
    const int wid  = tid >> 5;           // 0..3
    const int lane = tid & 31;
    const int h    = blockIdx.x;
    const int qt   = (int)gridDim.y - 1 - (int)blockIdx.y;   // long blocks first
    const int q0   = qt * 64;
    const int wq   = q0 + wid * 16;

    const uint32_t smb = smem_u32(sm);

    // ---- stage Q tile (64x64) into K area, extract A-fragments ----
    {
        const __half* qg = g_q16 + ((size_t)h * SEQ + q0) * DH;
#pragma unroll
        for (int i = 0; i < 4; i++) {
            int idx = i * 128 + tid;     // 0..511 chunks
            int row = idx >> 3;          // 0..63
            int g   = idx & 7;
            *(uint4*)(sm + row * KSTR + g * 8) = *((const uint4*)(qg + (size_t)row * DH) + g);
        }
    }
    __syncthreads();

    uint32_t qa[4][4];
    {
        int row  = wid * 16 + (lane & 15);
        int colh = (lane >> 4) * 8;
#pragma unroll
        for (int kb = 0; kb < 4; kb++)
            ldmx4(qa[kb], smb + (uint32_t)(row * KSTR + kb * 16 + colh) * 2);
    }
    __syncthreads();

    __half* smK = sm;
    __half* smV = sm + KVT128;

    float O[8][4];
#pragma unroll
    for (int d = 0; d < 8; d++)
#pragma unroll
        for (int j = 0; j < 4; j++) O[d][j] = 0.f;
    float m0 = NEG, m1 = NEG, l0 = 0.f, l1 = 0.f;

    const int kmax = (qt + 1) * 64;      // keys needed by this CTA
    for (int k0g = 0; k0g < kmax; k0g += 128) {
        // ---- stage 128 keys of K and V (always in-bounds) ----
        {
            const __half* kg = g_k16 + ((size_t)h * SEQ + k0g) * DH;
            const __half* vg = g_v16 + ((size_t)h * SEQ + k0g) * DH;
#pragma unroll
            for (int i = 0; i < 8; i++) {
                int idx = i * 128 + tid;     // 0..1023 chunks
                int row = idx >> 3;          // 0..127
                int g   = idx & 7;
                *(uint4*)(smK + row * KSTR + g * 8) = *((const uint4*)(kg + (size_t)row * DH) + g);
                *(uint4*)(smV + row * KSTR + g * 8) = *((const uint4*)(vg + (size_t)row * DH) + g);
            }
        }
        __syncthreads();

#pragma unroll
        for (int sub = 0; sub < 2; sub++) {
            const int k0 = k0g + sub * 64;
            if (k0 >= kmax) break;
            if (k0 > wq + 15) continue;   // fully masked for this warp (guard restored)
            const uint32_t smKb = smb + (uint32_t)(sub * 64 * KSTR) * 2;
            const uint32_t smVb = smb + (uint32_t)(KVT128 + sub * 64 * KSTR) * 2;

            // ---- S = Q @ K^T (exp2-domain, fp32 accum) ----
            float c[8][4];
#pragma unroll
            for (int nb = 0; nb < 8; nb++)
#pragma unroll
                for (int j = 0; j < 4; j++) c[nb][j] = 0.f;

#pragma unroll
            for (int nb = 0; nb < 8; nb++) {
                uint32_t kk[8];
                uint32_t rowa = nb * 8 + (lane & 7);
                uint32_t cola = (lane >> 3) * 8;
                ldmx4(kk,     smKb + (rowa * KSTR + cola) * 2);
                ldmx4(kk + 4, smKb + (rowa * KSTR + 32 + cola) * 2);
#pragma unroll
                for (int kb = 0; kb < 4; kb++)
                    mma16816(c[nb], qa[kb], kk + kb * 2, c[nb]);
            }

            // ---- causal mask (diagonal tiles only) ----
            if (k0 + 63 > wq) {
                int r0 = wq + (lane >> 2);
                int r1 = r0 + 8;
                int cb = k0 + (lane & 3) * 2;
#pragma unroll
                for (int nb = 0; nb < 8; nb++) {
                    int col = cb + nb * 8;
                    if (col     > r0) c[nb][0] = NEG;
                    if (col + 1 > r0) c[nb][1] = NEG;
                    if (col     > r1) c[nb][2] = NEG;
                    if (col + 1 > r1) c[nb][3] = NEG;
                }
            }

            // ---- online softmax (base-2, fp32 max, fp16x2 exp) ----
            float tm0 = NEG, tm1 = NEG;
#pragma unroll
            for (int nb = 0; nb < 8; nb++) {
                tm0 = fmaxf(tm0, fmaxf(c[nb][0], c[nb][1]));
                tm1 = fmaxf(tm1, fmaxf(c[nb][2], c[nb][3]));
            }
            tm0 = fmaxf(tm0, __shfl_xor_sync(0xffffffffu, tm0, 1));
            tm0 = fmaxf(tm0, __shfl_xor_sync(0xffffffffu, tm0, 2));
            tm1 = fmaxf(tm1, __shfl_xor_sync(0xffffffffu, tm1, 1));
            tm1 = fmaxf(tm1, __shfl_xor_sync(0xffffffffu, tm1, 2));

            float mn0 = fmaxf(m0, tm0), mn1 = fmaxf(m1, tm1);
            float a0  = ex2(m0 - mn0), a1 = ex2(m1 - mn1);

            // P = ex2(c - mn) as half2 pairs: e0 = rows r0, e1 = rows r1.
            // These ARE the P A-fragments (no repack).
            uint32_t e0[8], e1[8];
#pragma unroll
            for (int nb = 0; nb < 8; nb++) {
                e0[nb] = ex2h2(packh2(c[nb][0] - mn0, c[nb][1] - mn0));
                e1[nb] = ex2h2(packh2(c[nb][2] - mn1, c[nb][3] - mn1));
            }

            // row sums via HADD2 tree (pairwise for accuracy)
            __half2 s00 = __hadd2(__hadd2(u2h2(e0[0]), u2h2(e0[1])),
                                  __hadd2(u2h2(e0[2]), u2h2(e0[3])));
            __half2 s01 = __hadd2(__hadd2(u2h2(e0[4]), u2h2(e0[5])),
                                  __hadd2(u2h2(e0[6]), u2h2(e0[7])));
            __half2 s10 = __hadd2(__hadd2(u2h2(e1[0]), u2h2(e1[1])),
                                  __hadd2(u2h2(e1[2]), u2h2(e1[3])));
            __half2 s11 = __hadd2(__hadd2(u2h2(e1[4]), u2h2(e1[5])),
                                  __hadd2(u2h2(e1[6]), u2h2(e1[7])));
            float2 f0 = __half22float2(s00), f0b = __half22float2(s01);
            float2 f1 = __half22float2(s10), f1b = __half22float2(s11);
            float ps0 = (f0.x + f0.y) + (f0b.x + f0b.y);
            float ps1 = (f1.x + f1.y) + (f1b.x + f1b.y);

            ps0 += __shfl_xor_sync(0xffffffffu, ps0, 1);
            ps0 += __shfl_xor_sync(0xffffffffu, ps0, 2);
            ps1 += __shfl_xor_sync(0xffffffffu, ps1, 1);
            ps1 += __shfl_xor_sync(0xffffffffu, ps1, 2);
            l0 = l0 * a0 + ps0;  m0 = mn0;
            l1 = l1 * a1 + ps1;  m1 = mn1;

#pragma unroll
            for (int d = 0; d < 8; d++) {
                O[d][0] *= a0; O[d][1] *= a0;
                O[d][2] *= a1; O[d][3] *= a1;
            }

            // ---- P A-frags directly from e0/e1 ----
            uint32_t pa[4][4];
#pragma unroll
            for (int kb = 0; kb < 4; kb++) {
                pa[kb][0] = e0[2 * kb];
                pa[kb][1] = e1[2 * kb];
                pa[kb][2] = e0[2 * kb + 1];
                pa[kb][3] = e1[2 * kb + 1];
            }

            // ---- O += P @ V ----
#pragma unroll
            for (int db = 0; db < 8; db++) {
                uint32_t v0[4], v1[4];
                ldmx4t(v0, smVb + (uint32_t)((lane)      * KSTR + db * 8) * 2);
                ldmx4t(v1, smVb + (uint32_t)((32 + lane) * KSTR + db * 8) * 2);
                mma16816(O[db], pa[0], v0,     O[db]);
                mma16816(O[db], pa[1], v0 + 2, O[db]);
                mma16816(O[db], pa[2], v1,     O[db]);
                mma16816(O[db], pa[3], v1 + 2, O[db]);
            }
        }
        __syncthreads();   // all warps done with this 128-key stage
    }

    // ---- epilogue: divide by l, store fp16 for out-proj ----
    const float inv0 = 1.f / l0, inv1 = 1.f / l1;
    const int r0 = wq + (lane >> 2);
    const int r1 = r0 + 8;
    __half* o0 = g_attn16 + (size_t)r0 * DM + h * DH + (lane & 3) * 2;
    __half* o1 = g_attn16 + (size_t)r1 * DM + h * DH + (lane & 3) * 2;
#pragma unroll
    for (int db = 0; db < 8; db++) {
        *(__half2*)(o0 + db * 8) = __floats2half2_rn(O[db][0] * inv0, O[db][1] * inv0);
        *(__half2*)(o1 + db * 8) = __floats2half2_rn(O[db][2] * inv1, O[db][3] * inv1);
    }
}

// ---------------------------------------------------------------------------
extern "C" void kernel_launch(void* const* d_in, const int* in_sizes, int n_in,
                              void* d_out, int out_size)
{
    const float* x     = (const float*)d_in[0];
    const float* W_in  = (const float*)d_in[1];
    const float* b_in  = (const float*)d_in[2];
    const float* W_out = (const float*)d_in[3];
    const float* b_out = (const float*)d_in[4];
    float* out = (float*)d_out;

    __half *x16, *win16, *wout16, *attn16;
    cudaGetSymbolAddress((void**)&x16,    g_x16);
    cudaGetSymbolAddress((void**)&win16,  g_win16);
    cudaGetSymbolAddress((void**)&wout16, g_wout16);
    cudaGetSymbolAddress((void**)&attn16, g_attn16);

    // 0) fp32 -> fp16 converts (one launch for x, W_in, W_out)
    {
        int total = (CVT_S0 + CVT_S1 + CVT_S2) / 8;
        cvt_all<<<(total + 255) / 256, 256>>>(x, W_in, W_out);
    }
    // 1) QKV projection (128x128, 256 thr), scatter fp16 Q(scaled)/K/V per-head
    {
        dim3 grid(QKVC / 128, SEQ / 128);
        gemm_qkv<<<grid, 256>>>(x16, win16, b_in);
    }
    // 2) HMMA causal flash attention (64 q-rows, 128 thr, 128-key staging)
    {
        dim3 grid(NH, SEQ / 64);
        attn_mma_kernel<<<grid, 128>>>();
    }
    // 3) out = attn @ W_out^T + b_out (128x64 CTA, 4 warps of 64x32)
    {
        dim3 grid(DM / 64, SEQ / 128);
        gemm_out<<<grid, 128>>>(attn16, wout16, b_out, out);
    }
}

// round 14
// speedup vs baseline: 1.4534x; 1.4534x over previous
#include <cuda_runtime.h>
#include <cuda_fp16.h>
#include <math.h>
#include <cstdint>

#define SEQ   4096
#define DM    768
#define NH    12
#define DH    64
#define QKVC  2304          // 3 * DM
#define QS    0.18033688011112042f   // (1/sqrt(64)) * log2(e): exp2-domain scores
#define NEG   -1.0e30f

// ------------------------- scratch (__device__ globals) --------------------
__device__ __half g_x16[SEQ * DM];          // x in fp16
__device__ __half g_win16[QKVC * DM];       // W_in fp16
__device__ __half g_wout16[DM * DM];        // W_out fp16
__device__ __half g_q16[NH * SEQ * DH];     // [h][s][d], pre-scaled by QS
__device__ __half g_k16[NH * SEQ * DH];
__device__ __half g_v16[NH * SEQ * DH];
__device__ __half g_attn16[SEQ * DM];       // attention out fp16

// ---------------------------- PTX helpers ----------------------------------
__device__ __forceinline__ uint32_t smem_u32(const void* p) {
    uint32_t a;
    asm("{ .reg .u64 t; cvta.to.shared.u64 t, %1; cvt.u32.u64 %0, t; }" : "=r"(a) : "l"(p));
    return a;
}
__device__ __forceinline__ void ldmx4(uint32_t* r, uint32_t addr) {
    asm volatile("ldmatrix.sync.aligned.m8n8.x4.shared.b16 {%0,%1,%2,%3}, [%4];"
        : "=r"(r[0]), "=r"(r[1]), "=r"(r[2]), "=r"(r[3]) : "r"(addr));
}
__device__ __forceinline__ void ldmx4t(uint32_t* r, uint32_t addr) {
    asm volatile("ldmatrix.sync.aligned.m8n8.x4.trans.shared.b16 {%0,%1,%2,%3}, [%4];"
        : "=r"(r[0]), "=r"(r[1]), "=r"(r[2]), "=r"(r[3]) : "r"(addr));
}
__device__ __forceinline__ void mma16816(float* d, const uint32_t* a,
                                         const uint32_t* b, const float* c) {
    asm volatile(
        "mma.sync.aligned.m16n8k16.row.col.f32.f16.f16.f32 "
        "{%0,%1,%2,%3}, {%4,%5,%6,%7}, {%8,%9}, {%10,%11,%12,%13};"
        : "=f"(d[0]), "=f"(d[1]), "=f"(d[2]), "=f"(d[3])
        : "r"(a[0]), "r"(a[1]), "r"(a[2]), "r"(a[3]),
          "r"(b[0]), "r"(b[1]),
          "f"(c[0]), "f"(c[1]), "f"(c[2]), "f"(c[3]));
}
__device__ __forceinline__ uint32_t packh2(float x, float y) {
    __half2 h = __floats2half2_rn(x, y);
    return *(uint32_t*)&h;
}
__device__ __forceinline__ float ex2(float x) {           // raw MUFU.EX2
    float y;
    asm("ex2.approx.f32 %0, %1;" : "=f"(y) : "f"(x));
    return y;
}

#define GSTR 72   // smem row stride in halves (conflict-free ldmatrix + STS phases)

// ---------------------------------------------------------------------------
// fp32 -> fp16 convert, all three tensors in one launch (8 elems/thread)
// ---------------------------------------------------------------------------
#define CVT_S0 (SEQ * DM)
#define CVT_S1 (QKVC * DM)
#define CVT_S2 (DM * DM)

__device__ __forceinline__ void cvt8(const float* s, __half* d) {
    float4 a = *(const float4*)s;
    float4 b = *(const float4*)(s + 4);
    uint4 u;
    u.x = packh2(a.x, a.y); u.y = packh2(a.z, a.w);
    u.z = packh2(b.x, b.y); u.w = packh2(b.z, b.w);
    *(uint4*)d = u;
}

__global__ __launch_bounds__(256) void cvt_all(const float* __restrict__ x,
                                               const float* __restrict__ wi,
                                               const float* __restrict__ wo)
{
    int i = (blockIdx.x * 256 + threadIdx.x) * 8;
    if (i < CVT_S0) {
        cvt8(x + i, g_x16 + i);
    } else if (i < CVT_S0 + CVT_S1) {
        int j = i - CVT_S0;
        cvt8(wi + j, g_win16 + j);
    } else if (i < CVT_S0 + CVT_S1 + CVT_S2) {
        int j = i - CVT_S0 - CVT_S1;
        cvt8(wo + j, g_wout16 + j);
    }
}

// ---------------------------------------------------------------------------
// QKV GEMM (R11 winner): 128x128 CTA, 256 thr, warp 64x32, K-tile 64.
// ---------------------------------------------------------------------------
__global__ __launch_bounds__(256, 2) void gemm_qkv(
    const __half* __restrict__ A, const __half* __restrict__ B,
    const float* __restrict__ bias)
{
    __shared__ __half smA[128 * GSTR];
    __shared__ __half smB[128 * GSTR];

    const int tid  = threadIdx.x;
    const int lane = tid & 31;
    const int wid  = tid >> 5;
    const int m0   = blockIdx.y * 128;
    const int n0   = blockIdx.x * 128;
    const int wm   = (wid >> 2) * 64;
    const int wn   = (wid & 3) * 32;
    const int K    = DM;

    const uint32_t smAb = smem_u32(smA);
    const uint32_t smBb = smem_u32(smB);

    float Cf[4][4][4];
#pragma unroll
    for (int mt = 0; mt < 4; mt++)
#pragma unroll
        for (int nb = 0; nb < 4; nb++)
#pragma unroll
            for (int j = 0; j < 4; j++) Cf[mt][nb][j] = 0.f;

    for (int kt = 0; kt < K; kt += 64) {
#pragma unroll
        for (int i = 0; i < 4; i++) {
            int idx = i * 256 + tid;
            int row = idx >> 3;
            int g   = idx & 7;
            *(uint4*)(smA + row * GSTR + g * 8) =
                *(const uint4*)(A + (size_t)(m0 + row) * K + kt + g * 8);
            *(uint4*)(smB + row * GSTR + g * 8) =
                *(const uint4*)(B + (size_t)(n0 + row) * K + kt + g * 8);
        }
        __syncthreads();

        uint32_t bf[4][8];
#pragma unroll
        for (int nb = 0; nb < 4; nb++) {
            uint32_t rowa = wn + nb * 8 + (lane & 7);
            uint32_t cola = (lane >> 3) * 8;
            ldmx4(bf[nb],     smBb + (rowa * GSTR + cola) * 2);
            ldmx4(bf[nb] + 4, smBb + (rowa * GSTR + 32 + cola) * 2);
        }
#pragma unroll
        for (int mt = 0; mt < 4; mt++) {
            uint32_t af[4][4];
            uint32_t rowa = wm + mt * 16 + (lane & 15);
            uint32_t cola = (lane >> 4) * 8;
#pragma unroll
            for (int kb = 0; kb < 4; kb++)
                ldmx4(af[kb], smAb + (rowa * GSTR + kb * 16 + cola) * 2);
#pragma unroll
            for (int nb = 0; nb < 4; nb++)
#pragma unroll
                for (int kb = 0; kb < 4; kb++)
                    mma16816(Cf[mt][nb], af[kb], &bf[nb][2 * kb], Cf[mt][nb]);
        }
        __syncthreads();
    }

#pragma unroll
    for (int mt = 0; mt < 4; mt++) {
#pragma unroll
        for (int nb = 0; nb < 4; nb++) {
            int r0  = m0 + wm + mt * 16 + (lane >> 2);
            int col = n0 + wn + nb * 8 + (lane & 3) * 2;
            float b0v = bias[col], b1v = bias[col + 1];
            int seg  = col / DM;               // 0=Q 1=K 2=V
            int cm   = col - seg * DM;
            int head = cm >> 6, dim = cm & 63;
            __half* dst = (seg == 0) ? g_q16 : (seg == 1) ? g_k16 : g_v16;
            float sc = (seg == 0) ? QS : 1.f;
            __half2 w0 = __floats2half2_rn((Cf[mt][nb][0] + b0v) * sc,
                                           (Cf[mt][nb][1] + b1v) * sc);
            __half2 w1 = __floats2half2_rn((Cf[mt][nb][2] + b0v) * sc,
                                           (Cf[mt][nb][3] + b1v) * sc);
            *(__half2*)(dst + ((size_t)head * SEQ + r0) * DH + dim)     = w0;
            *(__half2*)(dst + ((size_t)head * SEQ + r0 + 8) * DH + dim) = w1;
        }
    }
}

// ---------------------------------------------------------------------------
// Out-proj GEMM (R12 winner): 128x64 CTA tile, 128 threads, 4 warps of 64x32.
// ---------------------------------------------------------------------------
__global__ __launch_bounds__(128, 4) void gemm_out(
    const __half* __restrict__ A, const __half* __restrict__ B,
    const float* __restrict__ bias, float* __restrict__ Cout)
{
    __shared__ __half smA[128 * GSTR];
    __shared__ __half smB[64 * GSTR];

    const int tid  = threadIdx.x;
    const int lane = tid & 31;
    const int wid  = tid >> 5;           // 0..3
    const int m0   = blockIdx.y * 128;
    const int n0   = blockIdx.x * 64;
    const int wm   = (wid >> 1) * 64;
    const int wn   = (wid & 1) * 32;
    const int K    = DM;
    const int N    = DM;

    const uint32_t smAb = smem_u32(smA);
    const uint32_t smBb = smem_u32(smB);

    float Cf[4][4][4];
#pragma unroll
    for (int mt = 0; mt < 4; mt++)
#pragma unroll
        for (int nb = 0; nb < 4; nb++)
#pragma unroll
            for (int j = 0; j < 4; j++) Cf[mt][nb][j] = 0.f;

    for (int kt = 0; kt < K; kt += 64) {
#pragma unroll
        for (int i = 0; i < 8; i++) {
            int idx = i * 128 + tid;
            int row = idx >> 3;
            int g   = idx & 7;
            *(uint4*)(smA + row * GSTR + g * 8) =
                *(const uint4*)(A + (size_t)(m0 + row) * K + kt + g * 8);
        }
#pragma unroll
        for (int i = 0; i < 4; i++) {
            int idx = i * 128 + tid;
            int row = idx >> 3;
            int g   = idx & 7;
            *(uint4*)(smB + row * GSTR + g * 8) =
                *(const uint4*)(B + (size_t)(n0 + row) * K + kt + g * 8);
        }
        __syncthreads();

        uint32_t bf[4][8];
#pragma unroll
        for (int nb = 0; nb < 4; nb++) {
            uint32_t rowa = wn + nb * 8 + (lane & 7);
            uint32_t cola = (lane >> 3) * 8;
            ldmx4(bf[nb],     smBb + (rowa * GSTR + cola) * 2);
            ldmx4(bf[nb] + 4, smBb + (rowa * GSTR + 32 + cola) * 2);
        }
#pragma unroll
        for (int mt = 0; mt < 4; mt++) {
            uint32_t af[4][4];
            uint32_t rowa = wm + mt * 16 + (lane & 15);
            uint32_t cola = (lane >> 4) * 8;
#pragma unroll
            for (int kb = 0; kb < 4; kb++)
                ldmx4(af[kb], smAb + (rowa * GSTR + kb * 16 + cola) * 2);
#pragma unroll
            for (int nb = 0; nb < 4; nb++)
#pragma unroll
                for (int kb = 0; kb < 4; kb++)
                    mma16816(Cf[mt][nb], af[kb], &bf[nb][2 * kb], Cf[mt][nb]);
        }
        __syncthreads();
    }

#pragma unroll
    for (int mt = 0; mt < 4; mt++) {
#pragma unroll
        for (int nb = 0; nb < 4; nb++) {
            int r0  = m0 + wm + mt * 16 + (lane >> 2);
            int col = n0 + wn + nb * 8 + (lane & 3) * 2;
            float b0v = bias[col], b1v = bias[col + 1];
            float2 w0 = make_float2(Cf[mt][nb][0] + b0v, Cf[mt][nb][1] + b1v);
            float2 w1 = make_float2(Cf[mt][nb][2] + b0v, Cf[mt][nb][3] + b1v);
            *(float2*)(Cout + (size_t)r0 * N + col)       = w0;
            *(float2*)(Cout + (size_t)(r0 + 8) * N + col) = w1;
        }
    }
}

// ---------------------------------------------------------------------------
// HMMA flash attention (R12 body + masked-tile skip guard ONLY).
// 128 threads (4 warps), 64 q-rows/CTA, 4 CTAs/SM, 128-key staging,
// two 64-key sub-blocks per barrier pair, scalar fp32 ex2 softmax.
// ---------------------------------------------------------------------------
#define KSTR 72
#define KVT128 (128 * KSTR)   // halves per 128-row K (or V) tile

__global__ __launch_bounds__(128, 4) void attn_mma_kernel()
{
    __shared__ __half sm[2 * KVT128];    // K[128] | V[128]  (36,864 B)

    const int tid  = threadIdx.x;
    const int wid  = tid >> 5;           // 0..3
    const int lane = tid & 31;
    const int h    = blockIdx.x;
    const int qt   = (int)gridDim.y - 1 - (int)blockIdx.y;   // long blocks first
    const int q0   = qt * 64;
    const int wq   = q0 + wid * 16;

    const uint32_t smb = smem_u32(sm);

    // ---- stage Q tile (64x64) into K area, extract A-fragments ----
    {
        const __half* qg = g_q16 + ((size_t)h * SEQ + q0) * DH;
#pragma unroll
        for (int i = 0; i < 4; i++) {
            int idx = i * 128 + tid;     // 0..511 chunks
            int row = idx >> 3;          // 0..63
            int g   = idx & 7;
            *(uint4*)(sm + row * KSTR + g * 8) = *((const uint4*)(qg + (size_t)row * DH) + g);
        }
    }
    __syncthreads();

    uint32_t qa[4][4];
    {
        int row  = wid * 16 + (lane & 15);
        int colh = (lane >> 4) * 8;
#pragma unroll
        for (int kb = 0; kb < 4; kb++)
            ldmx4(qa[kb], smb + (uint32_t)(row * KSTR + kb * 16 + colh) * 2);
    }
    __syncthreads();

    __half* smK = sm;
    __half* smV = sm + KVT128;

    float O[8][4];
#pragma unroll
    for (int d = 0; d < 8; d++)
#pragma unroll
        for (int j = 0; j < 4; j++) O[d][j] = 0.f;
    float m0 = NEG, m1 = NEG, l0 = 0.f, l1 = 0.f;

    const int kmax = (qt + 1) * 64;      // keys needed by this CTA
    for (int k0g = 0; k0g < kmax; k0g += 128) {
        // ---- stage 128 keys of K and V (always in-bounds) ----
        {
            const __half* kg = g_k16 + ((size_t)h * SEQ + k0g) * DH;
            const __half* vg = g_v16 + ((size_t)h * SEQ + k0g) * DH;
#pragma unroll
            for (int i = 0; i < 8; i++) {
                int idx = i * 128 + tid;     // 0..1023 chunks
                int row = idx >> 3;          // 0..127
                int g   = idx & 7;
                *(uint4*)(smK + row * KSTR + g * 8) = *((const uint4*)(kg + (size_t)row * DH) + g);
                *(uint4*)(smV + row * KSTR + g * 8) = *((const uint4*)(vg + (size_t)row * DH) + g);
            }
        }
        __syncthreads();

#pragma unroll
        for (int sub = 0; sub < 2; sub++) {
            const int k0 = k0g + sub * 64;
            if (k0 >= kmax) break;
            if (k0 <= wq + 15) {          // tile has at least one unmasked key
            const uint32_t smKb = smb + (uint32_t)(sub * 64 * KSTR) * 2;
            const uint32_t smVb = smb + (uint32_t)(KVT128 + sub * 64 * KSTR) * 2;

            // ---- S = Q @ K^T (exp2-domain) ----
            float c[8][4];
#pragma unroll
            for (int nb = 0; nb < 8; nb++)
#pragma unroll
                for (int j = 0; j < 4; j++) c[nb][j] = 0.f;

#pragma unroll
            for (int nb = 0; nb < 8; nb++) {
                uint32_t kk[8];
                uint32_t rowa = nb * 8 + (lane & 7);
                uint32_t cola = (lane >> 3) * 8;
                ldmx4(kk,     smKb + (rowa * KSTR + cola) * 2);
                ldmx4(kk + 4, smKb + (rowa * KSTR + 32 + cola) * 2);
#pragma unroll
                for (int kb = 0; kb < 4; kb++)
                    mma16816(c[nb], qa[kb], kk + kb * 2, c[nb]);
            }

            // ---- causal mask (diagonal tiles only) ----
            if (k0 + 63 > wq) {
                int r0 = wq + (lane >> 2);
                int r1 = r0 + 8;
                int cb = k0 + (lane & 3) * 2;
#pragma unroll
                for (int nb = 0; nb < 8; nb++) {
                    int col = cb + nb * 8;
                    if (col     > r0) c[nb][0] = NEG;
                    if (col + 1 > r0) c[nb][1] = NEG;
                    if (col     > r1) c[nb][2] = NEG;
                    if (col + 1 > r1) c[nb][3] = NEG;
                }
            }

            // ---- online softmax (base-2) ----
            float tm0 = NEG, tm1 = NEG;
#pragma unroll
            for (int nb = 0; nb < 8; nb++) {
                tm0 = fmaxf(tm0, fmaxf(c[nb][0], c[nb][1]));
                tm1 = fmaxf(tm1, fmaxf(c[nb][2], c[nb][3]));
            }
            tm0 = fmaxf(tm0, __shfl_xor_sync(0xffffffffu, tm0, 1));
            tm0 = fmaxf(tm0, __shfl_xor_sync(0xffffffffu, tm0, 2));
            tm1 = fmaxf(tm1, __shfl_xor_sync(0xffffffffu, tm1, 1));
            tm1 = fmaxf(tm1, __shfl_xor_sync(0xffffffffu, tm1, 2));

            float mn0 = fmaxf(m0, tm0), mn1 = fmaxf(m1, tm1);
            float a0  = ex2(m0 - mn0), a1 = ex2(m1 - mn1);
            float ps0 = 0.f, ps1 = 0.f;
#pragma unroll
            for (int nb = 0; nb < 8; nb++) {
                c[nb][0] = ex2(c[nb][0] - mn0);
                c[nb][1] = ex2(c[nb][1] - mn0);
                c[nb][2] = ex2(c[nb][2] - mn1);
                c[nb][3] = ex2(c[nb][3] - mn1);
                ps0 += c[nb][0] + c[nb][1];
                ps1 += c[nb][2] + c[nb][3];
            }
            ps0 += __shfl_xor_sync(0xffffffffu, ps0, 1);
            ps0 += __shfl_xor_sync(0xffffffffu, ps0, 2);
            ps1 += __shfl_xor_sync(0xffffffffu, ps1, 1);
            ps1 += __shfl_xor_sync(0xffffffffu, ps1, 2);
            l0 = l0 * a0 + ps0;  m0 = mn0;
            l1 = l1 * a1 + ps1;  m1 = mn1;

#pragma unroll
            for (int d = 0; d < 8; d++) {
                O[d][0] *= a0; O[d][1] *= a0;
                O[d][2] *= a1; O[d][3] *= a1;
            }

            // ---- repack P ----
            uint32_t pa[4][4];
#pragma unroll
            for (int kb = 0; kb < 4; kb++) {
                pa[kb][0] = packh2(c[2 * kb][0],     c[2 * kb][1]);
                pa[kb][1] = packh2(c[2 * kb][2],     c[2 * kb][3]);
                pa[kb][2] = packh2(c[2 * kb + 1][0], c[2 * kb + 1][1]);
                pa[kb][3] = packh2(c[2 * kb + 1][2], c[2 * kb + 1][3]);
            }

            // ---- O += P @ V ----
#pragma unroll
            for (int db = 0; db < 8; db++) {
                uint32_t v0[4], v1[4];
                ldmx4t(v0, smVb + (uint32_t)((lane)      * KSTR + db * 8) * 2);
                ldmx4t(v1, smVb + (uint32_t)((32 + lane) * KSTR + db * 8) * 2);
                mma16816(O[db], pa[0], v0,     O[db]);
                mma16816(O[db], pa[1], v0 + 2, O[db]);
                mma16816(O[db], pa[2], v1,     O[db]);
                mma16816(O[db], pa[3], v1 + 2, O[db]);
            }
            }   // end skip guard
        }
        __syncthreads();   // all warps done with this 128-key stage
    }

    // ---- epilogue: divide by l, store fp16 for out-proj ----
    const float inv0 = 1.f / l0, inv1 = 1.f / l1;
    const int r0 = wq + (lane >> 2);
    const int r1 = r0 + 8;
    __half* o0 = g_attn16 + (size_t)r0 * DM + h * DH + (lane & 3) * 2;
    __half* o1 = g_attn16 + (size_t)r1 * DM + h * DH + (lane & 3) * 2;
#pragma unroll
    for (int db = 0; db < 8; db++) {
        *(__half2*)(o0 + db * 8) = __floats2half2_rn(O[db][0] * inv0, O[db][1] * inv0);
        *(__half2*)(o1 + db * 8) = __floats2half2_rn(O[db][2] * inv1, O[db][3] * inv1);
    }
}

// ---------------------------------------------------------------------------
extern "C" void kernel_launch(void* const* d_in, const int* in_sizes, int n_in,
                              void* d_out, int out_size)
{
    const float* x     = (const float*)d_in[0];
    const float* W_in  = (const float*)d_in[1];
    const float* b_in  = (const float*)d_in[2];
    const float* W_out = (const float*)d_in[3];
    const float* b_out = (const float*)d_in[4];
    float* out = (float*)d_out;

    __half *x16, *win16, *wout16, *attn16;
    cudaGetSymbolAddress((void**)&x16,    g_x16);
    cudaGetSymbolAddress((void**)&win16,  g_win16);
    cudaGetSymbolAddress((void**)&wout16, g_wout16);
    cudaGetSymbolAddress((void**)&attn16, g_attn16);

    // 0) fp32 -> fp16 converts (one launch for x, W_in, W_out)
    {
        int total = (CVT_S0 + CVT_S1 + CVT_S2) / 8;
        cvt_all<<<(total + 255) / 256, 256>>>(x, W_in, W_out);
    }
    // 1) QKV projection (128x128, 256 thr), scatter fp16 Q(scaled)/K/V per-head
    {
        dim3 grid(QKVC / 128, SEQ / 128);
        gemm_qkv<<<grid, 256>>>(x16, win16, b_in);
    }
    // 2) HMMA causal flash attention (64 q-rows, 128 thr, 128-key staging)
    {
        dim3 grid(NH, SEQ / 64);
        attn_mma_kernel<<<grid, 128>>>();
    }
    // 3) out = attn @ W_out^T + b_out (128x64 CTA, 4 warps of 64x32)
    {
        dim3 grid(DM / 64, SEQ / 128);
        gemm_out<<<grid, 128>>>(attn16, wout16, b_out, out);
    }
}

// round 15
// speedup vs baseline: 1.5078x; 1.0374x over previous
#include <cuda_runtime.h>
#include <cuda_fp16.h>
#include <math.h>
#include <cstdint>

#define SEQ   4096
#define DM    768
#define NH    12
#define DH    64
#define QKVC  2304          // 3 * DM
#define QS    0.18033688011112042f   // (1/sqrt(64)) * log2(e): exp2-domain scores
#define NEG   -1.0e30f

// ------------------------- scratch (__device__ globals) --------------------
__device__ __half g_x16[SEQ * DM];          // x in fp16
__device__ __half g_win16[QKVC * DM];       // W_in fp16
__device__ __half g_wout16[DM * DM];        // W_out fp16
__device__ __half g_q16[NH * SEQ * DH];     // [h][s][d], pre-scaled by QS
__device__ __half g_k16[NH * SEQ * DH];
__device__ __half g_v16[NH * SEQ * DH];
__device__ __half g_attn16[SEQ * DM];       // attention out fp16

// ---------------------------- PTX helpers ----------------------------------
__device__ __forceinline__ uint32_t smem_u32(const void* p) {
    uint32_t a;
    asm("{ .reg .u64 t; cvta.to.shared.u64 t, %1; cvt.u32.u64 %0, t; }" : "=r"(a) : "l"(p));
    return a;
}
__device__ __forceinline__ void ldmx4(uint32_t* r, uint32_t addr) {
    asm volatile("ldmatrix.sync.aligned.m8n8.x4.shared.b16 {%0,%1,%2,%3}, [%4];"
        : "=r"(r[0]), "=r"(r[1]), "=r"(r[2]), "=r"(r[3]) : "r"(addr));
}
__device__ __forceinline__ void ldmx4t(uint32_t* r, uint32_t addr) {
    asm volatile("ldmatrix.sync.aligned.m8n8.x4.trans.shared.b16 {%0,%1,%2,%3}, [%4];"
        : "=r"(r[0]), "=r"(r[1]), "=r"(r[2]), "=r"(r[3]) : "r"(addr));
}
__device__ __forceinline__ void mma16816(float* d, const uint32_t* a,
                                         const uint32_t* b, const float* c) {
    asm volatile(
        "mma.sync.aligned.m16n8k16.row.col.f32.f16.f16.f32 "
        "{%0,%1,%2,%3}, {%4,%5,%6,%7}, {%8,%9}, {%10,%11,%12,%13};"
        : "=f"(d[0]), "=f"(d[1]), "=f"(d[2]), "=f"(d[3])
        : "r"(a[0]), "r"(a[1]), "r"(a[2]), "r"(a[3]),
          "r"(b[0]), "r"(b[1]),
          "f"(c[0]), "f"(c[1]), "f"(c[2]), "f"(c[3]));
}
__device__ __forceinline__ uint32_t packh2(float x, float y) {
    __half2 h = __floats2half2_rn(x, y);
    return *(uint32_t*)&h;
}
__device__ __forceinline__ float ex2(float x) {           // raw MUFU.EX2
    float y;
    asm("ex2.approx.f32 %0, %1;" : "=f"(y) : "f"(x));
    return y;
}
__device__ __forceinline__ uint32_t ex2h2(uint32_t x) {   // MUFU.EX2 on half2
    uint32_t y;
    asm("ex2.approx.f16x2 %0, %1;" : "=r"(y) : "r"(x));
    return y;
}
__device__ __forceinline__ __half2 u2h2(uint32_t x) { return *(__half2*)&x; }

#define GSTR 72   // smem row stride in halves (conflict-free ldmatrix + STS phases)

// ---------------------------------------------------------------------------
// fp32 -> fp16 convert, all three tensors in one launch (8 elems/thread)
// ---------------------------------------------------------------------------
#define CVT_S0 (SEQ * DM)
#define CVT_S1 (QKVC * DM)
#define CVT_S2 (DM * DM)

__device__ __forceinline__ void cvt8(const float* s, __half* d) {
    float4 a = *(const float4*)s;
    float4 b = *(const float4*)(s + 4);
    uint4 u;
    u.x = packh2(a.x, a.y); u.y = packh2(a.z, a.w);
    u.z = packh2(b.x, b.y); u.w = packh2(b.z, b.w);
    *(uint4*)d = u;
}

__global__ __launch_bounds__(256) void cvt_all(const float* __restrict__ x,
                                               const float* __restrict__ wi,
                                               const float* __restrict__ wo)
{
    int i = (blockIdx.x * 256 + threadIdx.x) * 8;
    if (i < CVT_S0) {
        cvt8(x + i, g_x16 + i);
    } else if (i < CVT_S0 + CVT_S1) {
        int j = i - CVT_S0;
        cvt8(wi + j, g_win16 + j);
    } else if (i < CVT_S0 + CVT_S1 + CVT_S2) {
        int j = i - CVT_S0 - CVT_S1;
        cvt8(wo + j, g_wout16 + j);
    }
}

// ---------------------------------------------------------------------------
// QKV GEMM (R11 winner): 128x128 CTA, 256 thr, warp 64x32, K-tile 64.
// ---------------------------------------------------------------------------
__global__ __launch_bounds__(256, 2) void gemm_qkv(
    const __half* __restrict__ A, const __half* __restrict__ B,
    const float* __restrict__ bias)
{
    __shared__ __half smA[128 * GSTR];
    __shared__ __half smB[128 * GSTR];

    const int tid  = threadIdx.x;
    const int lane = tid & 31;
    const int wid  = tid >> 5;
    const int m0   = blockIdx.y * 128;
    const int n0   = blockIdx.x * 128;
    const int wm   = (wid >> 2) * 64;
    const int wn   = (wid & 3) * 32;
    const int K    = DM;

    const uint32_t smAb = smem_u32(smA);
    const uint32_t smBb = smem_u32(smB);

    float Cf[4][4][4];
#pragma unroll
    for (int mt = 0; mt < 4; mt++)
#pragma unroll
        for (int nb = 0; nb < 4; nb++)
#pragma unroll
            for (int j = 0; j < 4; j++) Cf[mt][nb][j] = 0.f;

    for (int kt = 0; kt < K; kt += 64) {
#pragma unroll
        for (int i = 0; i < 4; i++) {
            int idx = i * 256 + tid;
            int row = idx >> 3;
            int g   = idx & 7;
            *(uint4*)(smA + row * GSTR + g * 8) =
                *(const uint4*)(A + (size_t)(m0 + row) * K + kt + g * 8);
            *(uint4*)(smB + row * GSTR + g * 8) =
                *(const uint4*)(B + (size_t)(n0 + row) * K + kt + g * 8);
        }
        __syncthreads();

        uint32_t bf[4][8];
#pragma unroll
        for (int nb = 0; nb < 4; nb++) {
            uint32_t rowa = wn + nb * 8 + (lane & 7);
            uint32_t cola = (lane >> 3) * 8;
            ldmx4(bf[nb],     smBb + (rowa * GSTR + cola) * 2);
            ldmx4(bf[nb] + 4, smBb + (rowa * GSTR + 32 + cola) * 2);
        }
#pragma unroll
        for (int mt = 0; mt < 4; mt++) {
            uint32_t af[4][4];
            uint32_t rowa = wm + mt * 16 + (lane & 15);
            uint32_t cola = (lane >> 4) * 8;
#pragma unroll
            for (int kb = 0; kb < 4; kb++)
                ldmx4(af[kb], smAb + (rowa * GSTR + kb * 16 + cola) * 2);
#pragma unroll
            for (int nb = 0; nb < 4; nb++)
#pragma unroll
                for (int kb = 0; kb < 4; kb++)
                    mma16816(Cf[mt][nb], af[kb], &bf[nb][2 * kb], Cf[mt][nb]);
        }
        __syncthreads();
    }

#pragma unroll
    for (int mt = 0; mt < 4; mt++) {
#pragma unroll
        for (int nb = 0; nb < 4; nb++) {
            int r0  = m0 + wm + mt * 16 + (lane >> 2);
            int col = n0 + wn + nb * 8 + (lane & 3) * 2;
            float b0v = bias[col], b1v = bias[col + 1];
            int seg  = col / DM;               // 0=Q 1=K 2=V
            int cm   = col - seg * DM;
            int head = cm >> 6, dim = cm & 63;
            __half* dst = (seg == 0) ? g_q16 : (seg == 1) ? g_k16 : g_v16;
            float sc = (seg == 0) ? QS : 1.f;
            __half2 w0 = __floats2half2_rn((Cf[mt][nb][0] + b0v) * sc,
                                           (Cf[mt][nb][1] + b1v) * sc);
            __half2 w1 = __floats2half2_rn((Cf[mt][nb][2] + b0v) * sc,
                                           (Cf[mt][nb][3] + b1v) * sc);
            *(__half2*)(dst + ((size_t)head * SEQ + r0) * DH + dim)     = w0;
            *(__half2*)(dst + ((size_t)head * SEQ + r0 + 8) * DH + dim) = w1;
        }
    }
}

// ---------------------------------------------------------------------------
// Out-proj GEMM (R12 winner): 128x64 CTA tile, 128 threads, 4 warps of 64x32.
// ---------------------------------------------------------------------------
__global__ __launch_bounds__(128, 4) void gemm_out(
    const __half* __restrict__ A, const __half* __restrict__ B,
    const float* __restrict__ bias, float* __restrict__ Cout)
{
    __shared__ __half smA[128 * GSTR];
    __shared__ __half smB[64 * GSTR];

    const int tid  = threadIdx.x;
    const int lane = tid & 31;
    const int wid  = tid >> 5;           // 0..3
    const int m0   = blockIdx.y * 128;
    const int n0   = blockIdx.x * 64;
    const int wm   = (wid >> 1) * 64;
    const int wn   = (wid & 1) * 32;
    const int K    = DM;
    const int N    = DM;

    const uint32_t smAb = smem_u32(smA);
    const uint32_t smBb = smem_u32(smB);

    float Cf[4][4][4];
#pragma unroll
    for (int mt = 0; mt < 4; mt++)
#pragma unroll
        for (int nb = 0; nb < 4; nb++)
#pragma unroll
            for (int j = 0; j < 4; j++) Cf[mt][nb][j] = 0.f;

    for (int kt = 0; kt < K; kt += 64) {
#pragma unroll
        for (int i = 0; i < 8; i++) {
            int idx = i * 128 + tid;
            int row = idx >> 3;
            int g   = idx & 7;
            *(uint4*)(smA + row * GSTR + g * 8) =
                *(const uint4*)(A + (size_t)(m0 + row) * K + kt + g * 8);
        }
#pragma unroll
        for (int i = 0; i < 4; i++) {
            int idx = i * 128 + tid;
            int row = idx >> 3;
            int g   = idx & 7;
            *(uint4*)(smB + row * GSTR + g * 8) =
                *(const uint4*)(B + (size_t)(n0 + row) * K + kt + g * 8);
        }
        __syncthreads();

        uint32_t bf[4][8];
#pragma unroll
        for (int nb = 0; nb < 4; nb++) {
            uint32_t rowa = wn + nb * 8 + (lane & 7);
            uint32_t cola = (lane >> 3) * 8;
            ldmx4(bf[nb],     smBb + (rowa * GSTR + cola) * 2);
            ldmx4(bf[nb] + 4, smBb + (rowa * GSTR + 32 + cola) * 2);
        }
#pragma unroll
        for (int mt = 0; mt < 4; mt++) {
            uint32_t af[4][4];
            uint32_t rowa = wm + mt * 16 + (lane & 15);
            uint32_t cola = (lane >> 4) * 8;
#pragma unroll
            for (int kb = 0; kb < 4; kb++)
                ldmx4(af[kb], smAb + (rowa * GSTR + kb * 16 + cola) * 2);
#pragma unroll
            for (int nb = 0; nb < 4; nb++)
#pragma unroll
                for (int kb = 0; kb < 4; kb++)
                    mma16816(Cf[mt][nb], af[kb], &bf[nb][2 * kb], Cf[mt][nb]);
        }
        __syncthreads();
    }

#pragma unroll
    for (int mt = 0; mt < 4; mt++) {
#pragma unroll
        for (int nb = 0; nb < 4; nb++) {
            int r0  = m0 + wm + mt * 16 + (lane >> 2);
            int col = n0 + wn + nb * 8 + (lane & 3) * 2;
            float b0v = bias[col], b1v = bias[col + 1];
            float2 w0 = make_float2(Cf[mt][nb][0] + b0v, Cf[mt][nb][1] + b1v);
            float2 w1 = make_float2(Cf[mt][nb][2] + b0v, Cf[mt][nb][3] + b1v);
            *(float2*)(Cout + (size_t)r0 * N + col)       = w0;
            *(float2*)(Cout + (size_t)(r0 + 8) * N + col) = w1;
        }
    }
}

// ---------------------------------------------------------------------------
// HMMA flash attention (R12 structure). 128 threads (4 warps), 64 q-rows/CTA,
// 4 CTAs/SM, 128-key staging, two 64-key sub-blocks per barrier pair.
// R15: f16x2 exponentials computed IN PLACE into pa[4][4] (same registers as
// R12's repack -> no live-range growth), fp32 subtract, fp32 sums from pa.
// ---------------------------------------------------------------------------
#define KSTR 72
#define KVT128 (128 * KSTR)   // halves per 128-row K (or V) tile

__global__ __launch_bounds__(128, 4) void attn_mma_kernel()
{
    __shared__ __half sm[2 * KVT128];    // K[128] | V[128]  (36,864 B)

    const int tid  = threadIdx.x;
    const int wid  = tid >> 5;           // 0..3
    const int lane = tid & 31;
    const int h    = blockIdx.x;
    const int qt   = (int)gridDim.y - 1 - (int)blockIdx.y;   // long blocks first
    const int q0   = qt * 64;
    const int wq   = q0 + wid * 16;

    const uint32_t smb = smem_u32(sm);

    // ---- stage Q tile (64x64) into K area, extract A-fragments ----
    {
        const __half* qg = g_q16 + ((size_t)h * SEQ + q0) * DH;
#pragma unroll
        for (int i = 0; i < 4; i++) {
            int idx = i * 128 + tid;     // 0..511 chunks
            int row = idx >> 3;          // 0..63
            int g   = idx & 7;
            *(uint4*)(sm + row * KSTR + g * 8) = *((const uint4*)(qg + (size_t)row * DH) + g);
        }
    }
    __syncthreads();

    uint32_t qa[4][4];
    {
        int row  = wid * 16 + (lane & 15);
        int colh = (lane >> 4) * 8;
#pragma unroll
        for (int kb = 0; kb < 4; kb++)
            ldmx4(qa[kb], smb + (uint32_t)(row * KSTR + kb * 16 + colh) * 2);
    }
    __syncthreads();

    __half* smK = sm;
    __half* smV = sm + KVT128;

    float O[8][4];
#pragma unroll
    for (int d = 0; d < 8; d++)
#pragma unroll
        for (int j = 0; j < 4; j++) O[d][j] = 0.f;
    float m0 = NEG, m1 = NEG, l0 = 0.f, l1 = 0.f;

    const int kmax = (qt + 1) * 64;      // keys needed by this CTA
    for (int k0g = 0; k0g < kmax; k0g += 128) {
        // ---- stage 128 keys of K and V (always in-bounds) ----
        {
            const __half* kg = g_k16 + ((size_t)h * SEQ + k0g) * DH;
            const __half* vg = g_v16 + ((size_t)h * SEQ + k0g) * DH;
#pragma unroll
            for (int i = 0; i < 8; i++) {
                int idx = i * 128 + tid;     // 0..1023 chunks
                int row = idx >> 3;          // 0..127
                int g   = idx & 7;
                *(uint4*)(smK + row * KSTR + g * 8) = *((const uint4*)(kg + (size_t)row * DH) + g);
                *(uint4*)(smV + row * KSTR + g * 8) = *((const uint4*)(vg + (size_t)row * DH) + g);
            }
        }
        __syncthreads();

#pragma unroll
        for (int sub = 0; sub < 2; sub++) {
            const int k0 = k0g + sub * 64;
            if (k0 >= kmax) break;
            const uint32_t smKb = smb + (uint32_t)(sub * 64 * KSTR) * 2;
            const uint32_t smVb = smb + (uint32_t)(KVT128 + sub * 64 * KSTR) * 2;

            // ---- S = Q @ K^T (exp2-domain) ----
            float c[8][4];
#pragma unroll
            for (int nb = 0; nb < 8; nb++)
#pragma unroll
                for (int j = 0; j < 4; j++) c[nb][j] = 0.f;

#pragma unroll
            for (int nb = 0; nb < 8; nb++) {
                uint32_t kk[8];
                uint32_t rowa = nb * 8 + (lane & 7);
                uint32_t cola = (lane >> 3) * 8;
                ldmx4(kk,     smKb + (rowa * KSTR + cola) * 2);
                ldmx4(kk + 4, smKb + (rowa * KSTR + 32 + cola) * 2);
#pragma unroll
                for (int kb = 0; kb < 4; kb++)
                    mma16816(c[nb], qa[kb], kk + kb * 2, c[nb]);
            }

            // ---- causal mask (diagonal tiles only) ----
            if (k0 + 63 > wq) {
                int r0 = wq + (lane >> 2);
                int r1 = r0 + 8;
                int cb = k0 + (lane & 3) * 2;
#pragma unroll
                for (int nb = 0; nb < 8; nb++) {
                    int col = cb + nb * 8;
                    if (col     > r0) c[nb][0] = NEG;
                    if (col + 1 > r0) c[nb][1] = NEG;
                    if (col     > r1) c[nb][2] = NEG;
                    if (col + 1 > r1) c[nb][3] = NEG;
                }
            }

            // ---- online softmax (base-2): fp32 max, f16x2 exp in place ----
            float tm0 = NEG, tm1 = NEG;
#pragma unroll
            for (int nb = 0; nb < 8; nb++) {
                tm0 = fmaxf(tm0, fmaxf(c[nb][0], c[nb][1]));
                tm1 = fmaxf(tm1, fmaxf(c[nb][2], c[nb][3]));
            }
            tm0 = fmaxf(tm0, __shfl_xor_sync(0xffffffffu, tm0, 1));
            tm0 = fmaxf(tm0, __shfl_xor_sync(0xffffffffu, tm0, 2));
            tm1 = fmaxf(tm1, __shfl_xor_sync(0xffffffffu, tm1, 1));
            tm1 = fmaxf(tm1, __shfl_xor_sync(0xffffffffu, tm1, 2));

            float mn0 = fmaxf(m0, tm0), mn1 = fmaxf(m1, tm1);
            float a0  = ex2(m0 - mn0), a1 = ex2(m1 - mn1);

            // P fragments: subtract in fp32, pack, exp2 in fp16x2.
            // pa layout matches R12 repack: [kb][0]=r0 lo keys, [1]=r1 lo,
            // [2]=r0 hi keys, [3]=r1 hi. c dies here (same live set as R12).
            uint32_t pa[4][4];
#pragma unroll
            for (int kb = 0; kb < 4; kb++) {
                pa[kb][0] = ex2h2(packh2(c[2 * kb][0]     - mn0, c[2 * kb][1]     - mn0));
                pa[kb][1] = ex2h2(packh2(c[2 * kb][2]     - mn1, c[2 * kb][3]     - mn1));
                pa[kb][2] = ex2h2(packh2(c[2 * kb + 1][0] - mn0, c[2 * kb + 1][1] - mn0));
                pa[kb][3] = ex2h2(packh2(c[2 * kb + 1][2] - mn1, c[2 * kb + 1][3] - mn1));
            }

            // row sums in fp32 from pa (l matches the exact fp16 P fed to MMA)
            float ps0 = 0.f, ps1 = 0.f;
#pragma unroll
            for (int kb = 0; kb < 4; kb++) {
                float2 x0 = __half22float2(u2h2(pa[kb][0]));
                float2 x2 = __half22float2(u2h2(pa[kb][2]));
                float2 x1 = __half22float2(u2h2(pa[kb][1]));
                float2 x3 = __half22float2(u2h2(pa[kb][3]));
                ps0 += (x0.x + x0.y) + (x2.x + x2.y);
                ps1 += (x1.x + x1.y) + (x3.x + x3.y);
            }
            ps0 += __shfl_xor_sync(0xffffffffu, ps0, 1);
            ps0 += __shfl_xor_sync(0xffffffffu, ps0, 2);
            ps1 += __shfl_xor_sync(0xffffffffu, ps1, 1);
            ps1 += __shfl_xor_sync(0xffffffffu, ps1, 2);
            l0 = l0 * a0 + ps0;  m0 = mn0;
            l1 = l1 * a1 + ps1;  m1 = mn1;

#pragma unroll
            for (int d = 0; d < 8; d++) {
                O[d][0] *= a0; O[d][1] *= a0;
                O[d][2] *= a1; O[d][3] *= a1;
            }

            // ---- O += P @ V ----
#pragma unroll
            for (int db = 0; db < 8; db++) {
                uint32_t v0[4], v1[4];
                ldmx4t(v0, smVb + (uint32_t)((lane)      * KSTR + db * 8) * 2);
                ldmx4t(v1, smVb + (uint32_t)((32 + lane) * KSTR + db * 8) * 2);
                mma16816(O[db], pa[0], v0,     O[db]);
                mma16816(O[db], pa[1], v0 + 2, O[db]);
                mma16816(O[db], pa[2], v1,     O[db]);
                mma16816(O[db], pa[3], v1 + 2, O[db]);
            }
        }
        __syncthreads();   // all warps done with this 128-key stage
    }

    // ---- epilogue: divide by l, store fp16 for out-proj ----
    const float inv0 = 1.f / l0, inv1 = 1.f / l1;
    const int r0 = wq + (lane >> 2);
    const int r1 = r0 + 8;
    __half* o0 = g_attn16 + (size_t)r0 * DM + h * DH + (lane & 3) * 2;
    __half* o1 = g_attn16 + (size_t)r1 * DM + h * DH + (lane & 3) * 2;
#pragma unroll
    for (int db = 0; db < 8; db++) {
        *(__half2*)(o0 + db * 8) = __floats2half2_rn(O[db][0] * inv0, O[db][1] * inv0);
        *(__half2*)(o1 + db * 8) = __floats2half2_rn(O[db][2] * inv1, O[db][3] * inv1);
    }
}

// ---------------------------------------------------------------------------
extern "C" void kernel_launch(void* const* d_in, const int* in_sizes, int n_in,
                              void* d_out, int out_size)
{
    const float* x     = (const float*)d_in[0];
    const float* W_in  = (const float*)d_in[1];
    const float* b_in  = (const float*)d_in[2];
    const float* W_out = (const float*)d_in[3];
    const float* b_out = (const float*)d_in[4];
    float* out = (float*)d_out;

    __half *x16, *win16, *wout16, *attn16;
    cudaGetSymbolAddress((void**)&x16,    g_x16);
    cudaGetSymbolAddress((void**)&win16,  g_win16);
    cudaGetSymbolAddress((void**)&wout16, g_wout16);
    cudaGetSymbolAddress((void**)&attn16, g_attn16);

    // 0) fp32 -> fp16 converts (one launch for x, W_in, W_out)
    {
        int total = (CVT_S0 + CVT_S1 + CVT_S2) / 8;
        cvt_all<<<(total + 255) / 256, 256>>>(x, W_in, W_out);
    }
    // 1) QKV projection (128x128, 256 thr), scatter fp16 Q(scaled)/K/V per-head
    {
        dim3 grid(QKVC / 128, SEQ / 128);
        gemm_qkv<<<grid, 256>>>(x16, win16, b_in);
    }
    // 2) HMMA causal flash attention (64 q-rows, 128 thr, 128-key staging)
    {
        dim3 grid(NH, SEQ / 64);
        attn_mma_kernel<<<grid, 128>>>();
    }
    // 3) out = attn @ W_out^T + b_out (128x64 CTA, 4 warps of 64x32)
    {
        dim3 grid(DM / 64, SEQ / 128);
        gemm_out<<<grid, 128>>>(attn16, wout16, b_out, out);
    }
}

// round 16
// speedup vs baseline: 1.5096x; 1.0012x over previous
#include <cuda_runtime.h>
#include <cuda_fp16.h>
#include <math.h>
#include <cstdint>

#define SEQ   4096
#define DM    768
#define NH    12
#define DH    64
#define QKVC  2304          // 3 * DM
#define QS    0.18033688011112042f   // (1/sqrt(64)) * log2(e): exp2-domain scores
#define NEG   -1.0e30f

// ------------------------- scratch (__device__ globals) --------------------
__device__ __half g_x16[SEQ * DM];          // x in fp16
__device__ __half g_win16[QKVC * DM];       // W_in fp16
__device__ __half g_wout16[DM * DM];        // W_out fp16
__device__ __half g_q16[NH * SEQ * DH];     // [h][s][d], pre-scaled by QS
__device__ __half g_k16[NH * SEQ * DH];
__device__ __half g_v16[NH * SEQ * DH];
__device__ __half g_attn16[SEQ * DM];       // attention out fp16

// ---------------------------- PTX helpers ----------------------------------
__device__ __forceinline__ uint32_t smem_u32(const void* p) {
    uint32_t a;
    asm("{ .reg .u64 t; cvta.to.shared.u64 t, %1; cvt.u32.u64 %0, t; }" : "=r"(a) : "l"(p));
    return a;
}
__device__ __forceinline__ void ldmx4(uint32_t* r, uint32_t addr) {
    asm volatile("ldmatrix.sync.aligned.m8n8.x4.shared.b16 {%0,%1,%2,%3}, [%4];"
        : "=r"(r[0]), "=r"(r[1]), "=r"(r[2]), "=r"(r[3]) : "r"(addr));
}
__device__ __forceinline__ void ldmx4t(uint32_t* r, uint32_t addr) {
    asm volatile("ldmatrix.sync.aligned.m8n8.x4.trans.shared.b16 {%0,%1,%2,%3}, [%4];"
        : "=r"(r[0]), "=r"(r[1]), "=r"(r[2]), "=r"(r[3]) : "r"(addr));
}
__device__ __forceinline__ void mma16816(float* d, const uint32_t* a,
                                         const uint32_t* b, const float* c) {
    asm volatile(
        "mma.sync.aligned.m16n8k16.row.col.f32.f16.f16.f32 "
        "{%0,%1,%2,%3}, {%4,%5,%6,%7}, {%8,%9}, {%10,%11,%12,%13};"
        : "=f"(d[0]), "=f"(d[1]), "=f"(d[2]), "=f"(d[3])
        : "r"(a[0]), "r"(a[1]), "r"(a[2]), "r"(a[3]),
          "r"(b[0]), "r"(b[1]),
          "f"(c[0]), "f"(c[1]), "f"(c[2]), "f"(c[3]));
}
__device__ __forceinline__ uint32_t packh2(float x, float y) {
    __half2 h = __floats2half2_rn(x, y);
    return *(uint32_t*)&h;
}
__device__ __forceinline__ float ex2(float x) {           // raw MUFU.EX2
    float y;
    asm("ex2.approx.f32 %0, %1;" : "=f"(y) : "f"(x));
    return y;
}
__device__ __forceinline__ uint32_t ex2h2(uint32_t x) {   // MUFU.EX2 on half2
    uint32_t y;
    asm("ex2.approx.f16x2 %0, %1;" : "=r"(y) : "r"(x));
    return y;
}
__device__ __forceinline__ __half2 u2h2(uint32_t x) { return *(__half2*)&x; }

#define GSTR  72    // attention smem row stride (halves)
#define GSTR2 136   // GEMM 128-K smem row stride (halves; 68 words mod 32 = 4, same skew)

// ---------------------------------------------------------------------------
// fp32 -> fp16 convert, all three tensors in one launch (8 elems/thread)
// ---------------------------------------------------------------------------
#define CVT_S0 (SEQ * DM)
#define CVT_S1 (QKVC * DM)
#define CVT_S2 (DM * DM)

__device__ __forceinline__ void cvt8(const float* s, __half* d) {
    float4 a = *(const float4*)s;
    float4 b = *(const float4*)(s + 4);
    uint4 u;
    u.x = packh2(a.x, a.y); u.y = packh2(a.z, a.w);
    u.z = packh2(b.x, b.y); u.w = packh2(b.z, b.w);
    *(uint4*)d = u;
}

__global__ __launch_bounds__(256) void cvt_all(const float* __restrict__ x,
                                               const float* __restrict__ wi,
                                               const float* __restrict__ wo)
{
    int i = (blockIdx.x * 256 + threadIdx.x) * 8;
    if (i < CVT_S0) {
        cvt8(x + i, g_x16 + i);
    } else if (i < CVT_S0 + CVT_S1) {
        int j = i - CVT_S0;
        cvt8(wi + j, g_win16 + j);
    } else if (i < CVT_S0 + CVT_S1 + CVT_S2) {
        int j = i - CVT_S0 - CVT_S1;
        cvt8(wo + j, g_wout16 + j);
    }
}

// ---------------------------------------------------------------------------
// QKV GEMM: 128x128 CTA, 256 thr, warp 64x32.
// R16: stage K=128 per barrier pair (dyn smem 69.6KB), compute 2x64 sub-chunks
// -> barriers 24 -> 12, LDG exposures halved.
// ---------------------------------------------------------------------------
__global__ __launch_bounds__(256, 2) void gemm_qkv(
    const __half* __restrict__ A, const __half* __restrict__ B,
    const float* __restrict__ bias)
{
    extern __shared__ __half smg[];
    __half* smA = smg;                    // 128 x GSTR2
    __half* smB = smg + 128 * GSTR2;      // 128 x GSTR2

    const int tid  = threadIdx.x;
    const int lane = tid & 31;
    const int wid  = tid >> 5;
    const int m0   = blockIdx.y * 128;
    const int n0   = blockIdx.x * 128;
    const int wm   = (wid >> 2) * 64;
    const int wn   = (wid & 3) * 32;
    const int K    = DM;

    const uint32_t smAb = smem_u32(smA);
    const uint32_t smBb = smem_u32(smB);

    float Cf[4][4][4];
#pragma unroll
    for (int mt = 0; mt < 4; mt++)
#pragma unroll
        for (int nb = 0; nb < 4; nb++)
#pragma unroll
            for (int j = 0; j < 4; j++) Cf[mt][nb][j] = 0.f;

    for (int kt = 0; kt < K; kt += 128) {
        // ---- stage A,B 128x128-half tiles ----
#pragma unroll
        for (int i = 0; i < 8; i++) {
            int idx = i * 256 + tid;          // 0..2047 16B chunks
            int row = idx >> 4;               // 0..127
            int g   = idx & 15;               // 0..15
            *(uint4*)(smA + row * GSTR2 + g * 8) =
                *(const uint4*)(A + (size_t)(m0 + row) * K + kt + g * 8);
            *(uint4*)(smB + row * GSTR2 + g * 8) =
                *(const uint4*)(B + (size_t)(n0 + row) * K + kt + g * 8);
        }
        __syncthreads();

#pragma unroll
        for (int sub = 0; sub < 2; sub++) {
            const uint32_t ko = sub * 64;     // half offset within row
            uint32_t bf[4][8];
#pragma unroll
            for (int nb = 0; nb < 4; nb++) {
                uint32_t rowa = wn + nb * 8 + (lane & 7);
                uint32_t cola = (lane >> 3) * 8;
                ldmx4(bf[nb],     smBb + (rowa * GSTR2 + ko + cola) * 2);
                ldmx4(bf[nb] + 4, smBb + (rowa * GSTR2 + ko + 32 + cola) * 2);
            }
#pragma unroll
            for (int mt = 0; mt < 4; mt++) {
                uint32_t af[4][4];
                uint32_t rowa = wm + mt * 16 + (lane & 15);
                uint32_t cola = (lane >> 4) * 8;
#pragma unroll
                for (int kb = 0; kb < 4; kb++)
                    ldmx4(af[kb], smAb + (rowa * GSTR2 + ko + kb * 16 + cola) * 2);
#pragma unroll
                for (int nb = 0; nb < 4; nb++)
#pragma unroll
                    for (int kb = 0; kb < 4; kb++)
                        mma16816(Cf[mt][nb], af[kb], &bf[nb][2 * kb], Cf[mt][nb]);
            }
        }
        __syncthreads();
    }

#pragma unroll
    for (int mt = 0; mt < 4; mt++) {
#pragma unroll
        for (int nb = 0; nb < 4; nb++) {
            int r0  = m0 + wm + mt * 16 + (lane >> 2);
            int col = n0 + wn + nb * 8 + (lane & 3) * 2;
            float b0v = bias[col], b1v = bias[col + 1];
            int seg  = col / DM;               // 0=Q 1=K 2=V
            int cm   = col - seg * DM;
            int head = cm >> 6, dim = cm & 63;
            __half* dst = (seg == 0) ? g_q16 : (seg == 1) ? g_k16 : g_v16;
            float sc = (seg == 0) ? QS : 1.f;
            __half2 w0 = __floats2half2_rn((Cf[mt][nb][0] + b0v) * sc,
                                           (Cf[mt][nb][1] + b1v) * sc);
            __half2 w1 = __floats2half2_rn((Cf[mt][nb][2] + b0v) * sc,
                                           (Cf[mt][nb][3] + b1v) * sc);
            *(__half2*)(dst + ((size_t)head * SEQ + r0) * DH + dim)     = w0;
            *(__half2*)(dst + ((size_t)head * SEQ + r0 + 8) * DH + dim) = w1;
        }
    }
}

// ---------------------------------------------------------------------------
// Out-proj GEMM: 128x64 CTA tile, 128 threads, 4 warps of 64x32.
// R16: K=128 staging (dyn smem 52.2KB, 4 CTAs/SM), 2x64 sub-chunks.
// ---------------------------------------------------------------------------
__global__ __launch_bounds__(128, 4) void gemm_out(
    const __half* __restrict__ A, const __half* __restrict__ B,
    const float* __restrict__ bias, float* __restrict__ Cout)
{
    extern __shared__ __half smg[];
    __half* smA = smg;                    // 128 x GSTR2
    __half* smB = smg + 128 * GSTR2;      // 64 x GSTR2

    const int tid  = threadIdx.x;
    const int lane = tid & 31;
    const int wid  = tid >> 5;           // 0..3
    const int m0   = blockIdx.y * 128;
    const int n0   = blockIdx.x * 64;
    const int wm   = (wid >> 1) * 64;
    const int wn   = (wid & 1) * 32;
    const int K    = DM;
    const int N    = DM;

    const uint32_t smAb = smem_u32(smA);
    const uint32_t smBb = smem_u32(smB);

    float Cf[4][4][4];
#pragma unroll
    for (int mt = 0; mt < 4; mt++)
#pragma unroll
        for (int nb = 0; nb < 4; nb++)
#pragma unroll
            for (int j = 0; j < 4; j++) Cf[mt][nb][j] = 0.f;

    for (int kt = 0; kt < K; kt += 128) {
#pragma unroll
        for (int i = 0; i < 16; i++) {              // A: 128 rows x 16 chunks
            int idx = i * 128 + tid;
            int row = idx >> 4;
            int g   = idx & 15;
            *(uint4*)(smA + row * GSTR2 + g * 8) =
                *(const uint4*)(A + (size_t)(m0 + row) * K + kt + g * 8);
        }
#pragma unroll
        for (int i = 0; i < 8; i++) {               // B: 64 rows x 16 chunks
            int idx = i * 128 + tid;
            int row = idx >> 4;
            int g   = idx & 15;
            *(uint4*)(smB + row * GSTR2 + g * 8) =
                *(const uint4*)(B + (size_t)(n0 + row) * K + kt + g * 8);
        }
        __syncthreads();

#pragma unroll
        for (int sub = 0; sub < 2; sub++) {
            const uint32_t ko = sub * 64;
            uint32_t bf[4][8];
#pragma unroll
            for (int nb = 0; nb < 4; nb++) {
                uint32_t rowa = wn + nb * 8 + (lane & 7);
                uint32_t cola = (lane >> 3) * 8;
                ldmx4(bf[nb],     smBb + (rowa * GSTR2 + ko + cola) * 2);
                ldmx4(bf[nb] + 4, smBb + (rowa * GSTR2 + ko + 32 + cola) * 2);
            }
#pragma unroll
            for (int mt = 0; mt < 4; mt++) {
                uint32_t af[4][4];
                uint32_t rowa = wm + mt * 16 + (lane & 15);
                uint32_t cola = (lane >> 4) * 8;
#pragma unroll
                for (int kb = 0; kb < 4; kb++)
                    ldmx4(af[kb], smAb + (rowa * GSTR2 + ko + kb * 16 + cola) * 2);
#pragma unroll
                for (int nb = 0; nb < 4; nb++)
#pragma unroll
                    for (int kb = 0; kb < 4; kb++)
                        mma16816(Cf[mt][nb], af[kb], &bf[nb][2 * kb], Cf[mt][nb]);
            }
        }
        __syncthreads();
    }

#pragma unroll
    for (int mt = 0; mt < 4; mt++) {
#pragma unroll
        for (int nb = 0; nb < 4; nb++) {
            int r0  = m0 + wm + mt * 16 + (lane >> 2);
            int col = n0 + wn + nb * 8 + (lane & 3) * 2;
            float b0v = bias[col], b1v = bias[col + 1];
            float2 w0 = make_float2(Cf[mt][nb][0] + b0v, Cf[mt][nb][1] + b1v);
            float2 w1 = make_float2(Cf[mt][nb][2] + b0v, Cf[mt][nb][3] + b1v);
            *(float2*)(Cout + (size_t)r0 * N + col)       = w0;
            *(float2*)(Cout + (size_t)(r0 + 8) * N + col) = w1;
        }
    }
}

// ---------------------------------------------------------------------------
// HMMA flash attention (R15 winner, unchanged). 128 threads (4 warps),
// 64 q-rows/CTA, 4 CTAs/SM, 128-key staging, 2x64-key sub-blocks,
// register-neutral f16x2 softmax.
// ---------------------------------------------------------------------------
#define KSTR 72
#define KVT128 (128 * KSTR)   // halves per 128-row K (or V) tile

__global__ __launch_bounds__(128, 4) void attn_mma_kernel()
{
    __shared__ __half sm[2 * KVT128];    // K[128] | V[128]  (36,864 B)

    const int tid  = threadIdx.x;
    const int wid  = tid >> 5;           // 0..3
    const int lane = tid & 31;
    const int h    = blockIdx.x;
    const int qt   = (int)gridDim.y - 1 - (int)blockIdx.y;   // long blocks first
    const int q0   = qt * 64;
    const int wq   = q0 + wid * 16;

    const uint32_t smb = smem_u32(sm);

    // ---- stage Q tile (64x64) into K area, extract A-fragments ----
    {
        const __half* qg = g_q16 + ((size_t)h * SEQ + q0) * DH;
#pragma unroll
        for (int i = 0; i < 4; i++) {
            int idx = i * 128 + tid;     // 0..511 chunks
            int row = idx >> 3;          // 0..63
            int g   = idx & 7;
            *(uint4*)(sm + row * KSTR + g * 8) = *((const uint4*)(qg + (size_t)row * DH) + g);
        }
    }
    __syncthreads();

    uint32_t qa[4][4];
    {
        int row  = wid * 16 + (lane & 15);
        int colh = (lane >> 4) * 8;
#pragma unroll
        for (int kb = 0; kb < 4; kb++)
            ldmx4(qa[kb], smb + (uint32_t)(row * KSTR + kb * 16 + colh) * 2);
    }
    __syncthreads();

    __half* smK = sm;
    __half* smV = sm + KVT128;

    float O[8][4];
#pragma unroll
    for (int d = 0; d < 8; d++)
#pragma unroll
        for (int j = 0; j < 4; j++) O[d][j] = 0.f;
    float m0 = NEG, m1 = NEG, l0 = 0.f, l1 = 0.f;

    const int kmax = (qt + 1) * 64;      // keys needed by this CTA
    for (int k0g = 0; k0g < kmax; k0g += 128) {
        {
            const __half* kg = g_k16 + ((size_t)h * SEQ + k0g) * DH;
            const __half* vg = g_v16 + ((size_t)h * SEQ + k0g) * DH;
#pragma unroll
            for (int i = 0; i < 8; i++) {
                int idx = i * 128 + tid;     // 0..1023 chunks
                int row = idx >> 3;          // 0..127
                int g   = idx & 7;
                *(uint4*)(smK + row * KSTR + g * 8) = *((const uint4*)(kg + (size_t)row * DH) + g);
                *(uint4*)(smV + row * KSTR + g * 8) = *((const uint4*)(vg + (size_t)row * DH) + g);
            }
        }
        __syncthreads();

#pragma unroll
        for (int sub = 0; sub < 2; sub++) {
            const int k0 = k0g + sub * 64;
            if (k0 >= kmax) break;
            const uint32_t smKb = smb + (uint32_t)(sub * 64 * KSTR) * 2;
            const uint32_t smVb = smb + (uint32_t)(KVT128 + sub * 64 * KSTR) * 2;

            // ---- S = Q @ K^T (exp2-domain) ----
            float c[8][4];
#pragma unroll
            for (int nb = 0; nb < 8; nb++)
#pragma unroll
                for (int j = 0; j < 4; j++) c[nb][j] = 0.f;

#pragma unroll
            for (int nb = 0; nb < 8; nb++) {
                uint32_t kk[8];
                uint32_t rowa = nb * 8 + (lane & 7);
                uint32_t cola = (lane >> 3) * 8;
                ldmx4(kk,     smKb + (rowa * KSTR + cola) * 2);
                ldmx4(kk + 4, smKb + (rowa * KSTR + 32 + cola) * 2);
#pragma unroll
                for (int kb = 0; kb < 4; kb++)
                    mma16816(c[nb], qa[kb], kk + kb * 2, c[nb]);
            }

            // ---- causal mask (diagonal tiles only) ----
            if (k0 + 63 > wq) {
                int r0 = wq + (lane >> 2);
                int r1 = r0 + 8;
                int cb = k0 + (lane & 3) * 2;
#pragma unroll
                for (int nb = 0; nb < 8; nb++) {
                    int col = cb + nb * 8;
                    if (col     > r0) c[nb][0] = NEG;
                    if (col + 1 > r0) c[nb][1] = NEG;
                    if (col     > r1) c[nb][2] = NEG;
                    if (col + 1 > r1) c[nb][3] = NEG;
                }
            }

            // ---- online softmax (base-2): fp32 max, f16x2 exp in place ----
            float tm0 = NEG, tm1 = NEG;
#pragma unroll
            for (int nb = 0; nb < 8; nb++) {
                tm0 = fmaxf(tm0, fmaxf(c[nb][0], c[nb][1]));
                tm1 = fmaxf(tm1, fmaxf(c[nb][2], c[nb][3]));
            }
            tm0 = fmaxf(tm0, __shfl_xor_sync(0xffffffffu, tm0, 1));
            tm0 = fmaxf(tm0, __shfl_xor_sync(0xffffffffu, tm0, 2));
            tm1 = fmaxf(tm1, __shfl_xor_sync(0xffffffffu, tm1, 1));
            tm1 = fmaxf(tm1, __shfl_xor_sync(0xffffffffu, tm1, 2));

            float mn0 = fmaxf(m0, tm0), mn1 = fmaxf(m1, tm1);
            float a0  = ex2(m0 - mn0), a1 = ex2(m1 - mn1);

            uint32_t pa[4][4];
#pragma unroll
            for (int kb = 0; kb < 4; kb++) {
                pa[kb][0] = ex2h2(packh2(c[2 * kb][0]     - mn0, c[2 * kb][1]     - mn0));
                pa[kb][1] = ex2h2(packh2(c[2 * kb][2]     - mn1, c[2 * kb][3]     - mn1));
                pa[kb][2] = ex2h2(packh2(c[2 * kb + 1][0] - mn0, c[2 * kb + 1][1] - mn0));
                pa[kb][3] = ex2h2(packh2(c[2 * kb + 1][2] - mn1, c[2 * kb + 1][3] - mn1));
            }

            float ps0 = 0.f, ps1 = 0.f;
#pragma unroll
            for (int kb = 0; kb < 4; kb++) {
                float2 x0 = __half22float2(u2h2(pa[kb][0]));
                float2 x2 = __half22float2(u2h2(pa[kb][2]));
                float2 x1 = __half22float2(u2h2(pa[kb][1]));
                float2 x3 = __half22float2(u2h2(pa[kb][3]));
                ps0 += (x0.x + x0.y) + (x2.x + x2.y);
                ps1 += (x1.x + x1.y) + (x3.x + x3.y);
            }
            ps0 += __shfl_xor_sync(0xffffffffu, ps0, 1);
            ps0 += __shfl_xor_sync(0xffffffffu, ps0, 2);
            ps1 += __shfl_xor_sync(0xffffffffu, ps1, 1);
            ps1 += __shfl_xor_sync(0xffffffffu, ps1, 2);
            l0 = l0 * a0 + ps0;  m0 = mn0;
            l1 = l1 * a1 + ps1;  m1 = mn1;

#pragma unroll
            for (int d = 0; d < 8; d++) {
                O[d][0] *= a0; O[d][1] *= a0;
                O[d][2] *= a1; O[d][3] *= a1;
            }

            // ---- O += P @ V ----
#pragma unroll
            for (int db = 0; db < 8; db++) {
                uint32_t v0[4], v1[4];
                ldmx4t(v0, smVb + (uint32_t)((lane)      * KSTR + db * 8) * 2);
                ldmx4t(v1, smVb + (uint32_t)((32 + lane) * KSTR + db * 8) * 2);
                mma16816(O[db], pa[0], v0,     O[db]);
                mma16816(O[db], pa[1], v0 + 2, O[db]);
                mma16816(O[db], pa[2], v1,     O[db]);
                mma16816(O[db], pa[3], v1 + 2, O[db]);
            }
        }
        __syncthreads();   // all warps done with this 128-key stage
    }

    // ---- epilogue: divide by l, store fp16 for out-proj ----
    const float inv0 = 1.f / l0, inv1 = 1.f / l1;
    const int r0 = wq + (lane >> 2);
    const int r1 = r0 + 8;
    __half* o0 = g_attn16 + (size_t)r0 * DM + h * DH + (lane & 3) * 2;
    __half* o1 = g_attn16 + (size_t)r1 * DM + h * DH + (lane & 3) * 2;
#pragma unroll
    for (int db = 0; db < 8; db++) {
        *(__half2*)(o0 + db * 8) = __floats2half2_rn(O[db][0] * inv0, O[db][1] * inv0);
        *(__half2*)(o1 + db * 8) = __floats2half2_rn(O[db][2] * inv1, O[db][3] * inv1);
    }
}

// ---------------------------------------------------------------------------
extern "C" void kernel_launch(void* const* d_in, const int* in_sizes, int n_in,
                              void* d_out, int out_size)
{
    const float* x     = (const float*)d_in[0];
    const float* W_in  = (const float*)d_in[1];
    const float* b_in  = (const float*)d_in[2];
    const float* W_out = (const float*)d_in[3];
    const float* b_out = (const float*)d_in[4];
    float* out = (float*)d_out;

    __half *x16, *win16, *wout16, *attn16;
    cudaGetSymbolAddress((void**)&x16,    g_x16);
    cudaGetSymbolAddress((void**)&win16,  g_win16);
    cudaGetSymbolAddress((void**)&wout16, g_wout16);
    cudaGetSymbolAddress((void**)&attn16, g_attn16);

    const int QKV_SMEM = 2 * 128 * GSTR2 * (int)sizeof(__half);          // 69,632 B
    const int OUT_SMEM = (128 + 64) * GSTR2 * (int)sizeof(__half);       // 52,224 B

    static bool attr_set = false;
    if (!attr_set) {
        cudaFuncSetAttribute(gemm_qkv,
                             cudaFuncAttributeMaxDynamicSharedMemorySize, QKV_SMEM);
        cudaFuncSetAttribute(gemm_out,
                             cudaFuncAttributeMaxDynamicSharedMemorySize, OUT_SMEM);
        attr_set = true;
    }

    // 0) fp32 -> fp16 converts (one launch for x, W_in, W_out)
    {
        int total = (CVT_S0 + CVT_S1 + CVT_S2) / 8;
        cvt_all<<<(total + 255) / 256, 256>>>(x, W_in, W_out);
    }
    // 1) QKV projection (128x128, 256 thr, K=128 staging)
    {
        dim3 grid(QKVC / 128, SEQ / 128);
        gemm_qkv<<<grid, 256, QKV_SMEM>>>(x16, win16, b_in);
    }
    // 2) HMMA causal flash attention (64 q-rows, 128 thr, 128-key staging)
    {
        dim3 grid(NH, SEQ / 64);
        attn_mma_kernel<<<grid, 128>>>();
    }
    // 3) out = attn @ W_out^T + b_out (128x64 CTA, K=128 staging)
    {
        dim3 grid(DM / 64, SEQ / 128);
        gemm_out<<<grid, 128, OUT_SMEM>>>(attn16, wout16, b_out, out);
    }
}